// round 3
// baseline (speedup 1.0000x reference)
#include <cuda_runtime.h>
#include <math.h>

#define D_MODEL  1024
#define N_HEADS  16
#define HEAD_DIM 64
#define BATCH    4
#define SEQ      2048
#define M_ROWS   (BATCH * SEQ)   // 8192

// ---------------------------------------------------------------------------
// Scratch (no cudaMalloc allowed). Q doubles as the attention output buffer:
// each attn thread consumes its Q row into registers before any O write, and
// Q rows are never read across threads. 3 x 32 MB fp32.
// ---------------------------------------------------------------------------
__device__ float g_Q[M_ROWS * D_MODEL];   // Q, then attention output
__device__ float g_K[M_ROWS * D_MODEL];
__device__ float g_V[M_ROWS * D_MODEL];

// ---------------------------------------------------------------------------
// SGEMM: C[m,n] = sum_k A[m,k] * W[n,k]   (torch-style weight: y = x @ W^T)
// Tiles: 128x128x8, 256 threads, 8x8 accumulator per thread.
// M=8192, N=1024, K=1024 -> all dims divide tile sizes; no bounds checks.
// ---------------------------------------------------------------------------
__device__ __forceinline__ void sgemm_body(const float* __restrict__ A,
                                           const float* __restrict__ W,
                                           float* __restrict__ C)
{
    const int K = D_MODEL, N = D_MODEL;
    __shared__ float As[8][128];
    __shared__ float Ws[8][128];

    const int bm  = blockIdx.y * 128;
    const int bn  = blockIdx.x * 128;
    const int tid = threadIdx.x;
    const int tx  = tid & 15;     // n direction
    const int ty  = tid >> 4;     // m direction

    const int lr = tid >> 1;            // 0..127
    const int lk = (tid & 1) * 4;       // 0 or 4

    float acc[8][8];
#pragma unroll
    for (int i = 0; i < 8; i++)
#pragma unroll
        for (int j = 0; j < 8; j++) acc[i][j] = 0.f;

    const float* aPtr = A + (size_t)(bm + lr) * K + lk;
    const float* wPtr = W + (size_t)(bn + lr) * K + lk;

#pragma unroll 1
    for (int k0 = 0; k0 < K; k0 += 8) {
        float4 a = *(const float4*)(aPtr + k0);
        float4 w = *(const float4*)(wPtr + k0);
        __syncthreads();
        As[lk + 0][lr] = a.x; As[lk + 1][lr] = a.y;
        As[lk + 2][lr] = a.z; As[lk + 3][lr] = a.w;
        Ws[lk + 0][lr] = w.x; Ws[lk + 1][lr] = w.y;
        Ws[lk + 2][lr] = w.z; Ws[lk + 3][lr] = w.w;
        __syncthreads();

#pragma unroll
        for (int kk = 0; kk < 8; kk++) {
            float ra[8], rw[8];
#pragma unroll
            for (int i = 0; i < 8; i++) ra[i] = As[kk][ty * 8 + i];
#pragma unroll
            for (int j = 0; j < 8; j++) rw[j] = Ws[kk][tx * 8 + j];
#pragma unroll
            for (int i = 0; i < 8; i++)
#pragma unroll
                for (int j = 0; j < 8; j++)
                    acc[i][j] = fmaf(ra[i], rw[j], acc[i][j]);
        }
    }

#pragma unroll
    for (int i = 0; i < 8; i++) {
        float* cp = C + (size_t)(bm + ty * 8 + i) * N + bn + tx * 8;
        *(float4*)(cp + 0) = make_float4(acc[i][0], acc[i][1], acc[i][2], acc[i][3]);
        *(float4*)(cp + 4) = make_float4(acc[i][4], acc[i][5], acc[i][6], acc[i][7]);
    }
}

// QKV fused: one kernel, blockIdx.z selects which weight/output.
__global__ void __launch_bounds__(256)
gemm_qkv(const float* __restrict__ x,
         const float* __restrict__ wq,
         const float* __restrict__ wk,
         const float* __restrict__ wv)
{
    const int which = blockIdx.z;
    const float* w = (which == 0) ? wq : (which == 1) ? wk : wv;
    float*       c = (which == 0) ? g_Q : (which == 1) ? g_K : g_V;
    sgemm_body(x, w, c);
}

__global__ void __launch_bounds__(256)
gemm_out(const float* __restrict__ wo, float* __restrict__ out)
{
    sgemm_body(g_Q, wo, out);   // g_Q holds attention output by now
}

// ---------------------------------------------------------------------------
// Causal flash attention, fp32. One query per thread, 128 queries per block,
// 64-key shared tiles. Lazy-rescale online softmax; causal early-break.
// Reads g_Q/g_K/g_V, writes output in place into g_Q.
// ---------------------------------------------------------------------------
#define QT 128
#define KT 64

__global__ void __launch_bounds__(128)
attn_kernel(const int* __restrict__ mask)
{
    const int qt  = blockIdx.x;
    const int h   = blockIdx.y;
    const int b   = blockIdx.z;
    const int tid = threadIdx.x;
    const int qi  = qt * QT + tid;

    __shared__ float Ks[KT][HEAD_DIM];
    __shared__ float Vs[KT][HEAD_DIM];
    __shared__ int   msk[KT];

    const float scale = 0.125f;   // 1/sqrt(64)

    float q[HEAD_DIM];
    {
        const float* qp = g_Q + (size_t)(b * SEQ + qi) * D_MODEL + h * HEAD_DIM;
#pragma unroll
        for (int d = 0; d < HEAD_DIM; d += 4) {
            float4 t = *(const float4*)(qp + d);
            q[d + 0] = t.x * scale; q[d + 1] = t.y * scale;
            q[d + 2] = t.z * scale; q[d + 3] = t.w * scale;
        }
    }

    float acc[HEAD_DIM];
#pragma unroll
    for (int d = 0; d < HEAD_DIM; d++) acc[d] = 0.f;
    float mrun = -1e30f;
    float lrun = 0.f;

    const int kmax = (qt + 1) * QT;

#pragma unroll 1
    for (int t0 = 0; t0 < kmax; t0 += KT) {
        __syncthreads();
        for (int i = tid; i < KT * 16; i += 128) {
            const int r = i >> 4;
            const int c = (i & 15) << 2;
            const size_t gro = (size_t)(b * SEQ + t0 + r) * D_MODEL + h * HEAD_DIM + c;
            *(float4*)&Ks[r][c] = *(const float4*)(g_K + gro);
            *(float4*)&Vs[r][c] = *(const float4*)(g_V + gro);
        }
        if (tid < KT) msk[tid] = mask[b * SEQ + t0 + tid];
        __syncthreads();

#pragma unroll 1
        for (int j = 0; j < KT; j++) {
            const int kg = t0 + j;
            if (kg > qi) break;       // causal
            if (!msk[j]) continue;    // attention_mask

            float s0 = 0.f, s1 = 0.f, s2 = 0.f, s3 = 0.f;
            const float4* kr = (const float4*)&Ks[j][0];
#pragma unroll
            for (int d4 = 0; d4 < 16; d4 += 4) {
                float4 k0 = kr[d4 + 0], k1 = kr[d4 + 1];
                float4 k2 = kr[d4 + 2], k3 = kr[d4 + 3];
                s0 = fmaf(q[4*d4 + 0],  k0.x, s0); s0 = fmaf(q[4*d4 + 1],  k0.y, s0);
                s0 = fmaf(q[4*d4 + 2],  k0.z, s0); s0 = fmaf(q[4*d4 + 3],  k0.w, s0);
                s1 = fmaf(q[4*d4 + 4],  k1.x, s1); s1 = fmaf(q[4*d4 + 5],  k1.y, s1);
                s1 = fmaf(q[4*d4 + 6],  k1.z, s1); s1 = fmaf(q[4*d4 + 7],  k1.w, s1);
                s2 = fmaf(q[4*d4 + 8],  k2.x, s2); s2 = fmaf(q[4*d4 + 9],  k2.y, s2);
                s2 = fmaf(q[4*d4 + 10], k2.z, s2); s2 = fmaf(q[4*d4 + 11], k2.w, s2);
                s3 = fmaf(q[4*d4 + 12], k3.x, s3); s3 = fmaf(q[4*d4 + 13], k3.y, s3);
                s3 = fmaf(q[4*d4 + 14], k3.z, s3); s3 = fmaf(q[4*d4 + 15], k3.w, s3);
            }
            const float s = (s0 + s1) + (s2 + s3);

            const float4* vr = (const float4*)&Vs[j][0];
            if (s > mrun) {
                const float corr = __expf(mrun - s);
                mrun = s;
                lrun = lrun * corr + 1.f;
#pragma unroll
                for (int d4 = 0; d4 < 16; d4++) {
                    float4 vv = vr[d4];
                    acc[4*d4 + 0] = fmaf(acc[4*d4 + 0], corr, vv.x);
                    acc[4*d4 + 1] = fmaf(acc[4*d4 + 1], corr, vv.y);
                    acc[4*d4 + 2] = fmaf(acc[4*d4 + 2], corr, vv.z);
                    acc[4*d4 + 3] = fmaf(acc[4*d4 + 3], corr, vv.w);
                }
            } else {
                const float p = __expf(s - mrun);
                lrun += p;
#pragma unroll
                for (int d4 = 0; d4 < 16; d4++) {
                    float4 vv = vr[d4];
                    acc[4*d4 + 0] = fmaf(p, vv.x, acc[4*d4 + 0]);
                    acc[4*d4 + 1] = fmaf(p, vv.y, acc[4*d4 + 1]);
                    acc[4*d4 + 2] = fmaf(p, vv.z, acc[4*d4 + 2]);
                    acc[4*d4 + 3] = fmaf(p, vv.w, acc[4*d4 + 3]);
                }
            }
        }
    }

    const float inv = 1.f / lrun;
    float* op = g_Q + (size_t)(b * SEQ + qi) * D_MODEL + h * HEAD_DIM;  // in-place
#pragma unroll
    for (int d = 0; d < HEAD_DIM; d += 4) {
        *(float4*)(op + d) = make_float4(acc[d+0]*inv, acc[d+1]*inv,
                                         acc[d+2]*inv, acc[d+3]*inv);
    }
}

// ---------------------------------------------------------------------------
// Launch: pure kernel launches, nothing else (maximally capture-safe).
// Inputs (metadata order): x, attention_mask, wq, wk, wv, wo
// ---------------------------------------------------------------------------
extern "C" void kernel_launch(void* const* d_in, const int* in_sizes, int n_in,
                              void* d_out, int out_size)
{
    const float* x    = (const float*)d_in[0];
    const int*   amsk = (const int*)  d_in[1];
    const float* wq   = (const float*)d_in[2];
    const float* wk   = (const float*)d_in[3];
    const float* wv   = (const float*)d_in[4];
    const float* wo   = (const float*)d_in[5];
    float*       out  = (float*)d_out;

    dim3 gQKV(D_MODEL / 128, M_ROWS / 128, 3);    // (8, 64, 3)
    gemm_qkv<<<gQKV, 256>>>(x, wq, wk, wv);

    dim3 gAttn(SEQ / QT, N_HEADS, BATCH);         // (16, 16, 4)
    attn_kernel<<<gAttn, 128>>>(amsk);

    dim3 gOut(D_MODEL / 128, M_ROWS / 128, 1);    // (8, 64)
    gemm_out<<<gOut, 256>>>(wo, out);
}

// round 5
// speedup vs baseline: 1.5055x; 1.5055x over previous
#include <cuda_runtime.h>
#include <cuda_bf16.h>
#include <cstdint>
#include <math.h>

#define D_MODEL  1024
#define N_HEADS  16
#define HEAD_DIM 64
#define BATCH    4
#define SEQ      2048
#define M_ROWS   (BATCH * SEQ)   // 8192
#define DD       (D_MODEL * D_MODEL)

// ---------------------------------------------------------------------------
// Static scratch (no cudaMalloc allowed)
// ---------------------------------------------------------------------------
__device__ float          g_Q [M_ROWS * D_MODEL];   // Q fp32, then attn output
__device__ float          g_K [M_ROWS * D_MODEL];
__device__ float          g_V [M_ROWS * D_MODEL];
__device__ __nv_bfloat16  g_XH[M_ROWS * D_MODEL];   // x (then AO) hi
__device__ __nv_bfloat16  g_XL[M_ROWS * D_MODEL];   // x (then AO) lo
__device__ __nv_bfloat16  g_WH[4 * DD];             // wq,wk,wv,wo hi
__device__ __nv_bfloat16  g_WL[4 * DD];             // wq,wk,wv,wo lo

// ---------------------------------------------------------------------------
// Helpers (compute_103-safe: no tcgen05 anywhere)
// ---------------------------------------------------------------------------
__device__ __forceinline__ uint32_t smem_u32(const void* p) {
    uint32_t a;
    asm("{ .reg .u64 t; cvta.to.shared.u64 t, %1; cvt.u32.u64 %0, t; }"
        : "=r"(a) : "l"(p));
    return a;
}
__device__ __forceinline__ void cp_async16(uint32_t dst, const void* src) {
    asm volatile("cp.async.cg.shared.global [%0], [%1], 16;\n"
                 :: "r"(dst), "l"(src) : "memory");
}
__device__ __forceinline__ void cp_commit() {
    asm volatile("cp.async.commit_group;\n" ::: "memory");
}
template <int N>
__device__ __forceinline__ void cp_wait() {
    asm volatile("cp.async.wait_group %0;\n" :: "n"(N) : "memory");
}
__device__ __forceinline__ void ldsm_x4(uint32_t addr, uint32_t* r) {
    asm volatile("ldmatrix.sync.aligned.m8n8.x4.shared.b16 {%0,%1,%2,%3}, [%4];\n"
                 : "=r"(r[0]), "=r"(r[1]), "=r"(r[2]), "=r"(r[3]) : "r"(addr));
}
__device__ __forceinline__ void mma16816(float* c, const uint32_t* a,
                                         uint32_t b0, uint32_t b1) {
    asm volatile(
        "mma.sync.aligned.m16n8k16.row.col.f32.bf16.bf16.f32 "
        "{%0,%1,%2,%3}, {%4,%5,%6,%7}, {%8,%9}, {%0,%1,%2,%3};\n"
        : "+f"(c[0]), "+f"(c[1]), "+f"(c[2]), "+f"(c[3])
        : "r"(a[0]), "r"(a[1]), "r"(a[2]), "r"(a[3]), "r"(b0), "r"(b1));
}

// ---------------------------------------------------------------------------
// Split conversion kernels: fp32 -> (bf16 hi, bf16 lo)
// ---------------------------------------------------------------------------
__device__ __forceinline__ void split4(float4 v, __nv_bfloat16* h, __nv_bfloat16* l,
                                       size_t idx4) {
    __nv_bfloat16 h0 = __float2bfloat16(v.x), h1 = __float2bfloat16(v.y);
    __nv_bfloat16 h2 = __float2bfloat16(v.z), h3 = __float2bfloat16(v.w);
    __nv_bfloat16 l0 = __float2bfloat16(v.x - __bfloat162float(h0));
    __nv_bfloat16 l1 = __float2bfloat16(v.y - __bfloat162float(h1));
    __nv_bfloat16 l2 = __float2bfloat16(v.z - __bfloat162float(h2));
    __nv_bfloat16 l3 = __float2bfloat16(v.w - __bfloat162float(h3));
    ((__nv_bfloat162*)h)[idx4 * 2 + 0] = __nv_bfloat162(h0, h1);
    ((__nv_bfloat162*)h)[idx4 * 2 + 1] = __nv_bfloat162(h2, h3);
    ((__nv_bfloat162*)l)[idx4 * 2 + 0] = __nv_bfloat162(l0, l1);
    ((__nv_bfloat162*)l)[idx4 * 2 + 1] = __nv_bfloat162(l2, l3);
}

__global__ void conv_x(const float* __restrict__ x) {
    size_t i = (size_t)blockIdx.x * blockDim.x + threadIdx.x;
    split4(((const float4*)x)[i], g_XH, g_XL, i);
}
__global__ void conv_w(const float* __restrict__ w0, const float* __restrict__ w1,
                       const float* __restrict__ w2, const float* __restrict__ w3) {
    const float* w = (blockIdx.z == 0) ? w0 : (blockIdx.z == 1) ? w1
                   : (blockIdx.z == 2) ? w2 : w3;
    size_t i = (size_t)blockIdx.x * blockDim.x + threadIdx.x;
    split4(((const float4*)w)[i], g_WH + (size_t)blockIdx.z * DD,
           g_WL + (size_t)blockIdx.z * DD, i);
}
__global__ void conv_ao() {
    size_t i = (size_t)blockIdx.x * blockDim.x + threadIdx.x;
    split4(((const float4*)g_Q)[i], g_XH, g_XL, i);
}

// ---------------------------------------------------------------------------
// Split-bf16 GEMM on mma.sync (HMMA): C[m,n] = sum_k A[m,k]*B[n,k], fp32 acc.
// 3 fused terms: Ah*Bh + Ah*Bl + Al*Bh over one K reduction.
// BM=BN=128, BK=64. 8 warps (2x4), warp tile 64x32, mma m16n8k16.
// SMEM: XOR-swizzled 16B chunks (chunk ^ (row&7)) -> conflict-free ldmatrix.
// cp.async double-buffered pipeline.
// ---------------------------------------------------------------------------
#define BK      64
#define NKT     (D_MODEL / BK)    // 16
#define NTILES  (3 * NKT)         // 48
#define A_BYTES (128 * 128)       // 16384
#define STAGE   (2 * A_BYTES)     // 32768
#define SM_TOTAL (2 * STAGE)      // 65536

__device__ __forceinline__ void gemm_core(const __nv_bfloat16* __restrict__ Bh,
                                          const __nv_bfloat16* __restrict__ Bl,
                                          float* __restrict__ C)
{
    extern __shared__ char smem[];
    const uint32_t sb = smem_u32(smem);
    const int tid = threadIdx.x;
    const int wid = tid >> 5, lid = tid & 31;
    const int wm  = wid >> 2, wn = wid & 3;          // 2 x 4 warp grid
    const int bm  = blockIdx.y * 128, bn = blockIdx.x * 128;

    const __nv_bfloat16* At[3] = { g_XH, g_XH, g_XL };
    const __nv_bfloat16* Bt[3] = { Bh,   Bl,   Bh   };

    // loader mapping: 2048 x 16B chunks per stage (A:1024, B:1024), 8/thread
    const int lw = tid >> 7;              // 0: first 1024 chunks, 1: second
    // per-lane fragment address components
    const int llo  = lid & 7;
    const int lr15 = lid & 15;
    const int lhiA = lid >> 4;            // A k-half
    const int lk8B = (lid >> 3) & 1;      // B k-half
    uint32_t aRow[4], bRow[2];
#pragma unroll
    for (int i = 0; i < 4; i++) aRow[i] = (uint32_t)(wm * 64 + i * 16 + lr15) * 128;
#pragma unroll
    for (int p = 0; p < 2; p++)
        bRow[p] = A_BYTES + (uint32_t)(wn * 32 + p * 16 + llo + ((lid >> 4) & 1) * 8) * 128;

    float acc[4][4][4];
#pragma unroll
    for (int i = 0; i < 4; i++)
#pragma unroll
        for (int j = 0; j < 4; j++)
#pragma unroll
            for (int q = 0; q < 4; q++) acc[i][j][q] = 0.f;

    auto issue = [&](int t) {
        const int term = t / NKT, kt = t % NKT;
        const __nv_bfloat16* Asrc = At[term] + (size_t)bm * D_MODEL + kt * BK;
        const __nv_bfloat16* Bsrc = Bt[term] + (size_t)bn * D_MODEL + kt * BK;
        const uint32_t st = sb + (uint32_t)(t & 1) * STAGE;
#pragma unroll
        for (int u = 0; u < 8; u++) {
            const int i = tid + u * 256;
            const int which = i >> 10;                // 0 = A, 1 = B
            const int j = i & 1023;
            const int r = j >> 3, c = j & 7;
            const __nv_bfloat16* src =
                (which ? Bsrc : Asrc) + (size_t)r * D_MODEL + c * 8;
            const uint32_t dst = st + (uint32_t)which * A_BYTES +
                                 (uint32_t)r * 128 + (uint32_t)((c ^ (r & 7)) << 4);
            cp_async16(dst, src);
        }
        cp_commit();
    };

    issue(0);
    issue(1);

#pragma unroll 1
    for (int t = 0; t < NTILES; t++) {
        if (t == NTILES - 1) cp_wait<0>(); else cp_wait<1>();
        __syncthreads();

        const uint32_t st = sb + (uint32_t)(t & 1) * STAGE;
#pragma unroll
        for (int s = 0; s < 4; s++) {
            const uint32_t offA = (uint32_t)(((2 * s + lhiA) ^ llo) << 4);
            const uint32_t offB = (uint32_t)(((2 * s + lk8B) ^ llo) << 4);
            uint32_t a[4][4], b[2][4];
#pragma unroll
            for (int i = 0; i < 4; i++) ldsm_x4(st + aRow[i] + offA, a[i]);
#pragma unroll
            for (int p = 0; p < 2; p++) ldsm_x4(st + bRow[p] + offB, b[p]);
#pragma unroll
            for (int i = 0; i < 4; i++)
#pragma unroll
                for (int j = 0; j < 4; j++)
                    mma16816(acc[i][j], a[i], b[j >> 1][(j & 1) * 2 + 0],
                                               b[j >> 1][(j & 1) * 2 + 1]);
        }
        __syncthreads();
        if (t + 2 < NTILES) issue(t + 2);
    }

    // epilogue: fp32 direct store
    const int g  = lid >> 2;
    const int t2 = (lid & 3) * 2;
#pragma unroll
    for (int i = 0; i < 4; i++) {
        const int row = bm + wm * 64 + i * 16 + g;
#pragma unroll
        for (int j = 0; j < 4; j++) {
            const int col = bn + wn * 32 + j * 8 + t2;
            *(float2*)&C[(size_t)row * D_MODEL + col] =
                make_float2(acc[i][j][0], acc[i][j][1]);
            *(float2*)&C[(size_t)(row + 8) * D_MODEL + col] =
                make_float2(acc[i][j][2], acc[i][j][3]);
        }
    }
}

__global__ void __launch_bounds__(256, 2)
gemm_qkv() {
    const int z = blockIdx.z;
    float* C = (z == 0) ? g_Q : (z == 1) ? g_K : g_V;
    gemm_core(g_WH + (size_t)z * DD, g_WL + (size_t)z * DD, C);
}
__global__ void __launch_bounds__(256, 2)
gemm_o(float* __restrict__ out) {
    gemm_core(g_WH + 3ull * DD, g_WL + 3ull * DD, out);
}

// ---------------------------------------------------------------------------
// Causal flash attention, fp32 (proven R3 kernel).
// Reads g_Q/g_K/g_V, writes output in place into g_Q.
// ---------------------------------------------------------------------------
#define QT 128
#define KT 64

__global__ void __launch_bounds__(128)
attn_kernel(const int* __restrict__ mask)
{
    const int qt  = blockIdx.x;
    const int h   = blockIdx.y;
    const int b   = blockIdx.z;
    const int tid = threadIdx.x;
    const int qi  = qt * QT + tid;

    __shared__ float Ks[KT][HEAD_DIM];
    __shared__ float Vs[KT][HEAD_DIM];
    __shared__ int   msk[KT];

    const float scale = 0.125f;

    float q[HEAD_DIM];
    {
        const float* qp = g_Q + (size_t)(b * SEQ + qi) * D_MODEL + h * HEAD_DIM;
#pragma unroll
        for (int d = 0; d < HEAD_DIM; d += 4) {
            float4 t = *(const float4*)(qp + d);
            q[d + 0] = t.x * scale; q[d + 1] = t.y * scale;
            q[d + 2] = t.z * scale; q[d + 3] = t.w * scale;
        }
    }

    float acc[HEAD_DIM];
#pragma unroll
    for (int d = 0; d < HEAD_DIM; d++) acc[d] = 0.f;
    float mrun = -1e30f;
    float lrun = 0.f;

    const int kmax = (qt + 1) * QT;

#pragma unroll 1
    for (int t0 = 0; t0 < kmax; t0 += KT) {
        __syncthreads();
        for (int i = tid; i < KT * 16; i += 128) {
            const int r = i >> 4;
            const int c = (i & 15) << 2;
            const size_t gro = (size_t)(b * SEQ + t0 + r) * D_MODEL + h * HEAD_DIM + c;
            *(float4*)&Ks[r][c] = *(const float4*)(g_K + gro);
            *(float4*)&Vs[r][c] = *(const float4*)(g_V + gro);
        }
        if (tid < KT) msk[tid] = mask[b * SEQ + t0 + tid];
        __syncthreads();

#pragma unroll 1
        for (int j = 0; j < KT; j++) {
            const int kg = t0 + j;
            if (kg > qi) break;
            if (!msk[j]) continue;

            float s0 = 0.f, s1 = 0.f, s2 = 0.f, s3 = 0.f;
            const float4* kr = (const float4*)&Ks[j][0];
#pragma unroll
            for (int d4 = 0; d4 < 16; d4 += 4) {
                float4 k0 = kr[d4 + 0], k1 = kr[d4 + 1];
                float4 k2 = kr[d4 + 2], k3 = kr[d4 + 3];
                s0 = fmaf(q[4*d4 + 0],  k0.x, s0); s0 = fmaf(q[4*d4 + 1],  k0.y, s0);
                s0 = fmaf(q[4*d4 + 2],  k0.z, s0); s0 = fmaf(q[4*d4 + 3],  k0.w, s0);
                s1 = fmaf(q[4*d4 + 4],  k1.x, s1); s1 = fmaf(q[4*d4 + 5],  k1.y, s1);
                s1 = fmaf(q[4*d4 + 6],  k1.z, s1); s1 = fmaf(q[4*d4 + 7],  k1.w, s1);
                s2 = fmaf(q[4*d4 + 8],  k2.x, s2); s2 = fmaf(q[4*d4 + 9],  k2.y, s2);
                s2 = fmaf(q[4*d4 + 10], k2.z, s2); s2 = fmaf(q[4*d4 + 11], k2.w, s2);
                s3 = fmaf(q[4*d4 + 12], k3.x, s3); s3 = fmaf(q[4*d4 + 13], k3.y, s3);
                s3 = fmaf(q[4*d4 + 14], k3.z, s3); s3 = fmaf(q[4*d4 + 15], k3.w, s3);
            }
            const float s = (s0 + s1) + (s2 + s3);

            const float4* vr = (const float4*)&Vs[j][0];
            if (s > mrun) {
                const float corr = __expf(mrun - s);
                mrun = s;
                lrun = lrun * corr + 1.f;
#pragma unroll
                for (int d4 = 0; d4 < 16; d4++) {
                    float4 vv = vr[d4];
                    acc[4*d4 + 0] = fmaf(acc[4*d4 + 0], corr, vv.x);
                    acc[4*d4 + 1] = fmaf(acc[4*d4 + 1], corr, vv.y);
                    acc[4*d4 + 2] = fmaf(acc[4*d4 + 2], corr, vv.z);
                    acc[4*d4 + 3] = fmaf(acc[4*d4 + 3], corr, vv.w);
                }
            } else {
                const float p = __expf(s - mrun);
                lrun += p;
#pragma unroll
                for (int d4 = 0; d4 < 16; d4++) {
                    float4 vv = vr[d4];
                    acc[4*d4 + 0] = fmaf(p, vv.x, acc[4*d4 + 0]);
                    acc[4*d4 + 1] = fmaf(p, vv.y, acc[4*d4 + 1]);
                    acc[4*d4 + 2] = fmaf(p, vv.z, acc[4*d4 + 2]);
                    acc[4*d4 + 3] = fmaf(p, vv.w, acc[4*d4 + 3]);
                }
            }
        }
    }

    const float inv = 1.f / lrun;
    float* op = g_Q + (size_t)(b * SEQ + qi) * D_MODEL + h * HEAD_DIM;
#pragma unroll
    for (int d = 0; d < HEAD_DIM; d += 4) {
        *(float4*)(op + d) = make_float4(acc[d+0]*inv, acc[d+1]*inv,
                                         acc[d+2]*inv, acc[d+3]*inv);
    }
}

// ---------------------------------------------------------------------------
// Launch. Inputs: x, attention_mask, wq, wk, wv, wo. Output fp32.
// ---------------------------------------------------------------------------
extern "C" void kernel_launch(void* const* d_in, const int* in_sizes, int n_in,
                              void* d_out, int out_size)
{
    const float* x    = (const float*)d_in[0];
    const int*   amsk = (const int*)  d_in[1];
    const float* wq   = (const float*)d_in[2];
    const float* wk   = (const float*)d_in[3];
    const float* wv   = (const float*)d_in[4];
    const float* wo   = (const float*)d_in[5];
    float*       out  = (float*)d_out;

    cudaFuncSetAttribute(gemm_qkv, cudaFuncAttributeMaxDynamicSharedMemorySize, SM_TOTAL);
    cudaFuncSetAttribute(gemm_o,   cudaFuncAttributeMaxDynamicSharedMemorySize, SM_TOTAL);

    conv_x<<<M_ROWS * D_MODEL / 4 / 256, 256>>>(x);
    conv_w<<<dim3(DD / 4 / 256, 1, 4), 256>>>(wq, wk, wv, wo);

    dim3 gQKV(D_MODEL / 128, M_ROWS / 128, 3);   // (8, 64, 3)
    gemm_qkv<<<gQKV, 256, SM_TOTAL>>>();

    dim3 gAttn(SEQ / QT, N_HEADS, BATCH);        // (16, 16, 4)
    attn_kernel<<<gAttn, 128>>>(amsk);

    conv_ao<<<M_ROWS * D_MODEL / 4 / 256, 256>>>();
    dim3 gOut(D_MODEL / 128, M_ROWS / 128, 1);
    gemm_o<<<gOut, 256, SM_TOTAL>>>(out);
}

// round 6
// speedup vs baseline: 2.6095x; 1.7333x over previous
#include <cuda_runtime.h>
#include <cuda_bf16.h>
#include <cstdint>
#include <math.h>

#define D_MODEL  1024
#define N_HEADS  16
#define HEAD_DIM 64
#define BATCH    4
#define SEQ      2048
#define M_ROWS   (BATCH * SEQ)   // 8192
#define DD       (D_MODEL * D_MODEL)

// ---------------------------------------------------------------------------
// Static scratch (no cudaMalloc allowed). All attention tensors split-bf16.
// ---------------------------------------------------------------------------
__device__ __nv_bfloat16 g_QH[M_ROWS * D_MODEL];
__device__ __nv_bfloat16 g_QL[M_ROWS * D_MODEL];
__device__ __nv_bfloat16 g_KH[M_ROWS * D_MODEL];
__device__ __nv_bfloat16 g_KL[M_ROWS * D_MODEL];
__device__ __nv_bfloat16 g_VH[M_ROWS * D_MODEL];
__device__ __nv_bfloat16 g_VL[M_ROWS * D_MODEL];
__device__ __nv_bfloat16 g_XH[M_ROWS * D_MODEL];   // x, then attn-out (hi)
__device__ __nv_bfloat16 g_XL[M_ROWS * D_MODEL];   // x, then attn-out (lo)
__device__ __nv_bfloat16 g_WH[4 * DD];             // wq,wk,wv,wo hi
__device__ __nv_bfloat16 g_WL[4 * DD];             // wq,wk,wv,wo lo

// ---------------------------------------------------------------------------
// Helpers (compute_103-safe)
// ---------------------------------------------------------------------------
__device__ __forceinline__ uint32_t smem_u32(const void* p) {
    uint32_t a;
    asm("{ .reg .u64 t; cvta.to.shared.u64 t, %1; cvt.u32.u64 %0, t; }"
        : "=r"(a) : "l"(p));
    return a;
}
__device__ __forceinline__ void cp_async16(uint32_t dst, const void* src) {
    asm volatile("cp.async.cg.shared.global [%0], [%1], 16;\n"
                 :: "r"(dst), "l"(src) : "memory");
}
__device__ __forceinline__ void cp_commit() {
    asm volatile("cp.async.commit_group;\n" ::: "memory");
}
template <int N>
__device__ __forceinline__ void cp_wait() {
    asm volatile("cp.async.wait_group %0;\n" :: "n"(N) : "memory");
}
__device__ __forceinline__ void ldsm_x4(uint32_t addr, uint32_t* r) {
    asm volatile("ldmatrix.sync.aligned.m8n8.x4.shared.b16 {%0,%1,%2,%3}, [%4];\n"
                 : "=r"(r[0]), "=r"(r[1]), "=r"(r[2]), "=r"(r[3]) : "r"(addr));
}
__device__ __forceinline__ void ldsm_x4t(uint32_t addr, uint32_t* r) {
    asm volatile("ldmatrix.sync.aligned.m8n8.x4.trans.shared.b16 {%0,%1,%2,%3}, [%4];\n"
                 : "=r"(r[0]), "=r"(r[1]), "=r"(r[2]), "=r"(r[3]) : "r"(addr));
}
__device__ __forceinline__ void mma16816(float* c, const uint32_t* a,
                                         uint32_t b0, uint32_t b1) {
    asm volatile(
        "mma.sync.aligned.m16n8k16.row.col.f32.bf16.bf16.f32 "
        "{%0,%1,%2,%3}, {%4,%5,%6,%7}, {%8,%9}, {%0,%1,%2,%3};\n"
        : "+f"(c[0]), "+f"(c[1]), "+f"(c[2]), "+f"(c[3])
        : "r"(a[0]), "r"(a[1]), "r"(a[2]), "r"(a[3]), "r"(b0), "r"(b1));
}
// pack (x -> low half, y -> high half), plus residual pack
__device__ __forceinline__ void packsplit(float x, float y,
                                          uint32_t& hi, uint32_t& lo) {
    __nv_bfloat162 H = __floats2bfloat162_rn(x, y);
    float2 Hf = __bfloat1622float2(H);
    __nv_bfloat162 L = __floats2bfloat162_rn(x - Hf.x, y - Hf.y);
    hi = *(uint32_t*)&H;
    lo = *(uint32_t*)&L;
}

// ---------------------------------------------------------------------------
// Split conversions for x and W
// ---------------------------------------------------------------------------
__device__ __forceinline__ void split4(float4 v, __nv_bfloat16* h, __nv_bfloat16* l,
                                       size_t idx4) {
    uint32_t h0, l0, h1, l1;
    packsplit(v.x, v.y, h0, l0);
    packsplit(v.z, v.w, h1, l1);
    ((uint32_t*)h)[idx4 * 2 + 0] = h0;
    ((uint32_t*)h)[idx4 * 2 + 1] = h1;
    ((uint32_t*)l)[idx4 * 2 + 0] = l0;
    ((uint32_t*)l)[idx4 * 2 + 1] = l1;
}
__global__ void conv_x(const float* __restrict__ x) {
    size_t i = (size_t)blockIdx.x * blockDim.x + threadIdx.x;
    split4(((const float4*)x)[i], g_XH, g_XL, i);
}
__global__ void conv_w(const float* __restrict__ w0, const float* __restrict__ w1,
                       const float* __restrict__ w2, const float* __restrict__ w3) {
    const float* w = (blockIdx.z == 0) ? w0 : (blockIdx.z == 1) ? w1
                   : (blockIdx.z == 2) ? w2 : w3;
    size_t i = (size_t)blockIdx.x * blockDim.x + threadIdx.x;
    split4(((const float4*)w)[i], g_WH + (size_t)blockIdx.z * DD,
           g_WL + (size_t)blockIdx.z * DD, i);
}

// ---------------------------------------------------------------------------
// Split-bf16 GEMM on mma.sync (verified in R5). Epilogue: fp32 OR split-bf16.
// ---------------------------------------------------------------------------
#define BK      64
#define NKT     (D_MODEL / BK)    // 16
#define NTILES  (3 * NKT)         // 48
#define A_BYTES (128 * 128)       // 16384
#define STAGE   (2 * A_BYTES)     // 32768
#define SM_GEMM (2 * STAGE)       // 65536

__device__ __forceinline__ void gemm_core(const __nv_bfloat16* __restrict__ Bh,
                                          const __nv_bfloat16* __restrict__ Bl,
                                          float* __restrict__ Cf,
                                          __nv_bfloat16* __restrict__ Ch,
                                          __nv_bfloat16* __restrict__ Cl,
                                          float scl)
{
    extern __shared__ char smem[];
    const uint32_t sb = smem_u32(smem);
    const int tid = threadIdx.x;
    const int wid = tid >> 5, lid = tid & 31;
    const int wm  = wid >> 2, wn = wid & 3;
    const int bm  = blockIdx.y * 128, bn = blockIdx.x * 128;

    const __nv_bfloat16* At[3] = { g_XH, g_XH, g_XL };
    const __nv_bfloat16* Bt[3] = { Bh,   Bl,   Bh   };

    const int llo  = lid & 7;
    const int lr15 = lid & 15;
    const int lhiA = lid >> 4;
    const int lk8B = (lid >> 3) & 1;
    uint32_t aRow[4], bRow[2];
#pragma unroll
    for (int i = 0; i < 4; i++) aRow[i] = (uint32_t)(wm * 64 + i * 16 + lr15) * 128;
#pragma unroll
    for (int p = 0; p < 2; p++)
        bRow[p] = A_BYTES + (uint32_t)(wn * 32 + p * 16 + llo + ((lid >> 4) & 1) * 8) * 128;

    float acc[4][4][4];
#pragma unroll
    for (int i = 0; i < 4; i++)
#pragma unroll
        for (int j = 0; j < 4; j++)
#pragma unroll
            for (int q = 0; q < 4; q++) acc[i][j][q] = 0.f;

    auto issue = [&](int t) {
        const int term = t / NKT, kt = t % NKT;
        const __nv_bfloat16* Asrc = At[term] + (size_t)bm * D_MODEL + kt * BK;
        const __nv_bfloat16* Bsrc = Bt[term] + (size_t)bn * D_MODEL + kt * BK;
        const uint32_t st = sb + (uint32_t)(t & 1) * STAGE;
#pragma unroll
        for (int u = 0; u < 8; u++) {
            const int i = tid + u * 256;
            const int which = i >> 10;
            const int j = i & 1023;
            const int r = j >> 3, c = j & 7;
            const __nv_bfloat16* src =
                (which ? Bsrc : Asrc) + (size_t)r * D_MODEL + c * 8;
            const uint32_t dst = st + (uint32_t)which * A_BYTES +
                                 (uint32_t)r * 128 + (uint32_t)((c ^ (r & 7)) << 4);
            cp_async16(dst, src);
        }
        cp_commit();
    };

    issue(0);
    issue(1);

#pragma unroll 1
    for (int t = 0; t < NTILES; t++) {
        if (t == NTILES - 1) cp_wait<0>(); else cp_wait<1>();
        __syncthreads();

        const uint32_t st = sb + (uint32_t)(t & 1) * STAGE;
#pragma unroll
        for (int s = 0; s < 4; s++) {
            const uint32_t offA = (uint32_t)(((2 * s + lhiA) ^ llo) << 4);
            const uint32_t offB = (uint32_t)(((2 * s + lk8B) ^ llo) << 4);
            uint32_t a[4][4], b[2][4];
#pragma unroll
            for (int i = 0; i < 4; i++) ldsm_x4(st + aRow[i] + offA, a[i]);
#pragma unroll
            for (int p = 0; p < 2; p++) ldsm_x4(st + bRow[p] + offB, b[p]);
#pragma unroll
            for (int i = 0; i < 4; i++)
#pragma unroll
                for (int j = 0; j < 4; j++)
                    mma16816(acc[i][j], a[i], b[j >> 1][(j & 1) * 2 + 0],
                                               b[j >> 1][(j & 1) * 2 + 1]);
        }
        __syncthreads();
        if (t + 2 < NTILES) issue(t + 2);
    }

    const int g  = lid >> 2;
    const int t2 = (lid & 3) * 2;
#pragma unroll
    for (int i = 0; i < 4; i++) {
        const int row = bm + wm * 64 + i * 16 + g;
#pragma unroll
        for (int j = 0; j < 4; j++) {
            const int col = bn + wn * 32 + j * 8 + t2;
            if (Cf) {
                *(float2*)&Cf[(size_t)row * D_MODEL + col] =
                    make_float2(acc[i][j][0], acc[i][j][1]);
                *(float2*)&Cf[(size_t)(row + 8) * D_MODEL + col] =
                    make_float2(acc[i][j][2], acc[i][j][3]);
            } else {
                uint32_t h, l;
                packsplit(acc[i][j][0] * scl, acc[i][j][1] * scl, h, l);
                *(uint32_t*)&Ch[(size_t)row * D_MODEL + col] = h;
                *(uint32_t*)&Cl[(size_t)row * D_MODEL + col] = l;
                packsplit(acc[i][j][2] * scl, acc[i][j][3] * scl, h, l);
                *(uint32_t*)&Ch[(size_t)(row + 8) * D_MODEL + col] = h;
                *(uint32_t*)&Cl[(size_t)(row + 8) * D_MODEL + col] = l;
            }
        }
    }
}

__global__ void __launch_bounds__(256, 2)
gemm_qkv() {
    const int z = blockIdx.z;
    __nv_bfloat16* Ch = (z == 0) ? g_QH : (z == 1) ? g_KH : g_VH;
    __nv_bfloat16* Cl = (z == 0) ? g_QL : (z == 1) ? g_KL : g_VL;
    const float scl = (z == 0) ? 0.125f : 1.0f;      // fold 1/sqrt(64) into Q
    gemm_core(g_WH + (size_t)z * DD, g_WL + (size_t)z * DD, nullptr, Ch, Cl, scl);
}
__global__ void __launch_bounds__(256, 2)
gemm_o(float* __restrict__ out) {
    gemm_core(g_WH + 3ull * DD, g_WL + 3ull * DD, out, nullptr, nullptr, 1.f);
}

// ---------------------------------------------------------------------------
// Tensor-core causal flash attention (split-bf16, fp32 softmax/accum).
// Block: 64 queries x one (b,h); 4 warps, 16 query rows each. 64-key tiles.
// SMEM stage: KH|KL|VH|VL (4 x 8KB) + mask(256B), double-buffered; Q staged once.
// ---------------------------------------------------------------------------
#define AST 33024                         // stage stride bytes
#define SM_ATTN (16384 + 2 * AST)         // 82432

__global__ void __launch_bounds__(128)
attn_mma(const int* __restrict__ mask)
{
    extern __shared__ char smem[];
    const uint32_t sb = smem_u32(smem);
    const int tid = threadIdx.x, wid = tid >> 5, lid = tid & 31;
    const int qt = blockIdx.x, h = blockIdx.y, b = blockIdx.z;
    const int bm = qt * 64;
    const int nt = qt + 1;                // causal: key tiles 0..qt

    // ---- stage Q tile (QH|QL), build A-fragments, keep in registers ----
    {
#pragma unroll
        for (int u = 0; u < 8; u++) {
            const int i = tid + u * 128;          // 0..1023
            const int arr = i >> 9;               // 0 QH, 1 QL
            const int j = i & 511;
            const int r = j >> 3, c = j & 7;
            const __nv_bfloat16* src = (arr ? g_QL : g_QH) +
                (size_t)(b * SEQ + bm + r) * D_MODEL + h * HEAD_DIM + c * 8;
            cp_async16(sb + (uint32_t)arr * 8192 +
                       (uint32_t)r * 128 + (uint32_t)((c ^ (r & 7)) << 4), src);
        }
        cp_commit();
        cp_wait<0>();
        __syncthreads();
    }
    uint32_t aQh[4][4], aQl[4][4];
#pragma unroll
    for (int ks = 0; ks < 4; ks++) {
        const uint32_t off = (uint32_t)(wid * 16 + (lid & 15)) * 128 +
                             (uint32_t)(((2 * ks + (lid >> 4)) ^ (lid & 7)) << 4);
        ldsm_x4(sb + off, aQh[ks]);
        ldsm_x4(sb + 8192 + off, aQl[ks]);
    }
    __syncthreads();

    auto issueKV = [&](int ti) {
        const uint32_t st = sb + 16384u + (uint32_t)(ti & 1) * AST;
        const int t0 = ti * 64;
#pragma unroll
        for (int u = 0; u < 16; u++) {
            const int i = tid + u * 128;          // 0..2047
            const int arr = i >> 9;               // 0 KH 1 KL 2 VH 3 VL
            const int j = i & 511;
            const int r = j >> 3, c = j & 7;
            const __nv_bfloat16* base = (arr == 0) ? g_KH : (arr == 1) ? g_KL
                                      : (arr == 2) ? g_VH : g_VL;
            const __nv_bfloat16* src = base +
                (size_t)(b * SEQ + t0 + r) * D_MODEL + h * HEAD_DIM + c * 8;
            cp_async16(st + (uint32_t)arr * 8192 +
                       (uint32_t)r * 128 + (uint32_t)((c ^ (r & 7)) << 4), src);
        }
        if (tid < 16)
            cp_async16(st + 32768 + tid * 16, mask + b * SEQ + t0 + tid * 4);
        cp_commit();
    };

    issueKV(0);
    if (nt > 1) issueKV(1);

    float oreg[8][4];
#pragma unroll
    for (int j = 0; j < 8; j++)
#pragma unroll
        for (int q = 0; q < 4; q++) oreg[j][q] = 0.f;
    float mA = -1e30f, mB = -1e30f, lA = 0.f, lB = 0.f;
    const int q0 = bm + wid * 16 + (lid >> 2);    // row A global q; row B = q0+8

#pragma unroll 1
    for (int ti = 0; ti < nt; ti++) {
        if (ti == nt - 1) cp_wait<0>(); else cp_wait<1>();
        __syncthreads();
        const uint32_t st = sb + 16384u + (uint32_t)(ti & 1) * AST;
        const int* msk_s = (const int*)(smem + 16384 + (ti & 1) * AST + 32768);
        const int t0 = ti * 64;

        // ---- S = Q @ K^T (3 split terms) ----
        float sr[8][4];
#pragma unroll
        for (int j = 0; j < 8; j++)
#pragma unroll
            for (int q = 0; q < 4; q++) sr[j][q] = 0.f;
#pragma unroll
        for (int ks = 0; ks < 4; ks++) {
            uint32_t bh[4][4], bl[4][4];
#pragma unroll
            for (int nb = 0; nb < 4; nb++) {
                const uint32_t row = (uint32_t)(nb * 16 + (lid & 7) + ((lid >> 4) & 1) * 8);
                const uint32_t off = row * 128 +
                    (uint32_t)(((2 * ks + ((lid >> 3) & 1)) ^ (lid & 7)) << 4);
                ldsm_x4(st + off, bh[nb]);
                ldsm_x4(st + 8192 + off, bl[nb]);
            }
#pragma unroll
            for (int j = 0; j < 8; j++) {
                const uint32_t b0h = bh[j >> 1][(j & 1) * 2], b1h = bh[j >> 1][(j & 1) * 2 + 1];
                const uint32_t b0l = bl[j >> 1][(j & 1) * 2], b1l = bl[j >> 1][(j & 1) * 2 + 1];
                mma16816(sr[j], aQh[ks], b0h, b1h);
                mma16816(sr[j], aQh[ks], b0l, b1l);
                mma16816(sr[j], aQl[ks], b0h, b1h);
            }
        }

        // ---- mask + online softmax ----
        const bool diag = (ti == qt);
#pragma unroll
        for (int j = 0; j < 8; j++) {
            const int c = j * 8 + (lid & 3) * 2;      // tile-local key col
            const int kg = t0 + c;
            const int mk0 = msk_s[c], mk1 = msk_s[c + 1];
            if (!mk0) { sr[j][0] = -1e30f; sr[j][2] = -1e30f; }
            if (!mk1) { sr[j][1] = -1e30f; sr[j][3] = -1e30f; }
            if (diag) {
                if (kg     > q0)     sr[j][0] = -1e30f;
                if (kg + 1 > q0)     sr[j][1] = -1e30f;
                if (kg     > q0 + 8) sr[j][2] = -1e30f;
                if (kg + 1 > q0 + 8) sr[j][3] = -1e30f;
            }
        }
        float tmA = -1e30f, tmB = -1e30f;
#pragma unroll
        for (int j = 0; j < 8; j++) {
            tmA = fmaxf(tmA, fmaxf(sr[j][0], sr[j][1]));
            tmB = fmaxf(tmB, fmaxf(sr[j][2], sr[j][3]));
        }
        tmA = fmaxf(tmA, __shfl_xor_sync(0xffffffff, tmA, 1));
        tmA = fmaxf(tmA, __shfl_xor_sync(0xffffffff, tmA, 2));
        tmB = fmaxf(tmB, __shfl_xor_sync(0xffffffff, tmB, 1));
        tmB = fmaxf(tmB, __shfl_xor_sync(0xffffffff, tmB, 2));
        const float nmA = fmaxf(mA, tmA), nmB = fmaxf(mB, tmB);
        const float corrA = __expf(mA - nmA), corrB = __expf(mB - nmB);
        mA = nmA; mB = nmB;
        float sA = 0.f, sB = 0.f;
#pragma unroll
        for (int j = 0; j < 8; j++) {
            sr[j][0] = __expf(sr[j][0] - nmA);
            sr[j][1] = __expf(sr[j][1] - nmA);
            sr[j][2] = __expf(sr[j][2] - nmB);
            sr[j][3] = __expf(sr[j][3] - nmB);
            sA += sr[j][0] + sr[j][1];
            sB += sr[j][2] + sr[j][3];
        }
        sA += __shfl_xor_sync(0xffffffff, sA, 1);
        sA += __shfl_xor_sync(0xffffffff, sA, 2);
        sB += __shfl_xor_sync(0xffffffff, sB, 1);
        sB += __shfl_xor_sync(0xffffffff, sB, 2);
        lA = lA * corrA + sA;
        lB = lB * corrB + sB;
#pragma unroll
        for (int j = 0; j < 8; j++) {
            oreg[j][0] *= corrA; oreg[j][1] *= corrA;
            oreg[j][2] *= corrB; oreg[j][3] *= corrB;
        }

        // ---- O += P @ V (3 split terms) ----
#pragma unroll
        for (int ks = 0; ks < 4; ks++) {
            uint32_t aph[4], apl[4];
            packsplit(sr[2*ks][0],   sr[2*ks][1],   aph[0], apl[0]);
            packsplit(sr[2*ks][2],   sr[2*ks][3],   aph[1], apl[1]);
            packsplit(sr[2*ks+1][0], sr[2*ks+1][1], aph[2], apl[2]);
            packsplit(sr[2*ks+1][2], sr[2*ks+1][3], aph[3], apl[3]);
            uint32_t vh[4][4], vl[4][4];
#pragma unroll
            for (int nb = 0; nb < 4; nb++) {
                const uint32_t row = (uint32_t)(ks * 16 + (lid & 7) + ((lid >> 3) & 1) * 8);
                const uint32_t chk = (uint32_t)(nb * 2 + (lid >> 4));
                const uint32_t off = row * 128 + ((chk ^ (lid & 7)) << 4);
                ldsm_x4t(st + 16384 + off, vh[nb]);
                ldsm_x4t(st + 24576 + off, vl[nb]);
            }
#pragma unroll
            for (int j = 0; j < 8; j++) {
                const uint32_t b0h = vh[j >> 1][(j & 1) * 2], b1h = vh[j >> 1][(j & 1) * 2 + 1];
                const uint32_t b0l = vl[j >> 1][(j & 1) * 2], b1l = vl[j >> 1][(j & 1) * 2 + 1];
                mma16816(oreg[j], aph, b0h, b1h);
                mma16816(oreg[j], apl, b0h, b1h);
                mma16816(oreg[j], aph, b0l, b1l);
            }
        }

        __syncthreads();
        if (ti + 2 < nt) issueKV(ti + 2);
    }

    // ---- epilogue: normalize, split to bf16 h/l, write to g_XH/g_XL ----
    const float invA = 1.f / lA, invB = 1.f / lB;
    const size_t rA = (size_t)(b * SEQ + q0) * D_MODEL + h * HEAD_DIM;
    const size_t rB = rA + 8ull * D_MODEL;
#pragma unroll
    for (int j = 0; j < 8; j++) {
        const int col = j * 8 + (lid & 3) * 2;
        uint32_t hh, ll;
        packsplit(oreg[j][0] * invA, oreg[j][1] * invA, hh, ll);
        *(uint32_t*)&g_XH[rA + col] = hh;
        *(uint32_t*)&g_XL[rA + col] = ll;
        packsplit(oreg[j][2] * invB, oreg[j][3] * invB, hh, ll);
        *(uint32_t*)&g_XH[rB + col] = hh;
        *(uint32_t*)&g_XL[rB + col] = ll;
    }
}

// ---------------------------------------------------------------------------
// Launch. Inputs: x, attention_mask, wq, wk, wv, wo. Output fp32.
// ---------------------------------------------------------------------------
extern "C" void kernel_launch(void* const* d_in, const int* in_sizes, int n_in,
                              void* d_out, int out_size)
{
    const float* x    = (const float*)d_in[0];
    const int*   amsk = (const int*)  d_in[1];
    const float* wq   = (const float*)d_in[2];
    const float* wk   = (const float*)d_in[3];
    const float* wv   = (const float*)d_in[4];
    const float* wo   = (const float*)d_in[5];
    float*       out  = (float*)d_out;

    cudaFuncSetAttribute(gemm_qkv, cudaFuncAttributeMaxDynamicSharedMemorySize, SM_GEMM);
    cudaFuncSetAttribute(gemm_o,   cudaFuncAttributeMaxDynamicSharedMemorySize, SM_GEMM);
    cudaFuncSetAttribute(attn_mma, cudaFuncAttributeMaxDynamicSharedMemorySize, SM_ATTN);

    conv_x<<<M_ROWS * D_MODEL / 4 / 256, 256>>>(x);
    conv_w<<<dim3(DD / 4 / 256, 1, 4), 256>>>(wq, wk, wv, wo);

    dim3 gQKV(D_MODEL / 128, M_ROWS / 128, 3);   // (8, 64, 3)
    gemm_qkv<<<gQKV, 256, SM_GEMM>>>();

    dim3 gAttn(SEQ / 64, N_HEADS, BATCH);        // (32, 16, 4)
    attn_mma<<<gAttn, 128, SM_ATTN>>>(amsk);

    dim3 gOut(D_MODEL / 128, M_ROWS / 128, 1);
    gemm_o<<<gOut, 256, SM_GEMM>>>(out);
}

// round 7
// speedup vs baseline: 3.9621x; 1.5183x over previous
#include <cuda_runtime.h>
#include <cuda_bf16.h>
#include <cstdint>
#include <math.h>

#define D_MODEL  1024
#define N_HEADS  16
#define HEAD_DIM 64
#define BATCH    4
#define SEQ      2048
#define M_ROWS   (BATCH * SEQ)   // 8192
#define DD       (D_MODEL * D_MODEL)

// ---------------------------------------------------------------------------
// Static scratch (no cudaMalloc allowed). All attention tensors split-bf16.
// ---------------------------------------------------------------------------
__device__ __nv_bfloat16 g_QH[M_ROWS * D_MODEL];
__device__ __nv_bfloat16 g_QL[M_ROWS * D_MODEL];
__device__ __nv_bfloat16 g_KH[M_ROWS * D_MODEL];
__device__ __nv_bfloat16 g_KL[M_ROWS * D_MODEL];
__device__ __nv_bfloat16 g_VH[M_ROWS * D_MODEL];
__device__ __nv_bfloat16 g_VL[M_ROWS * D_MODEL];
__device__ __nv_bfloat16 g_XH[M_ROWS * D_MODEL];   // x, then attn-out (hi)
__device__ __nv_bfloat16 g_XL[M_ROWS * D_MODEL];   // x, then attn-out (lo)
__device__ __nv_bfloat16 g_WH[4 * DD];             // wq,wk,wv,wo hi
__device__ __nv_bfloat16 g_WL[4 * DD];             // wq,wk,wv,wo lo

// ---------------------------------------------------------------------------
// Helpers (compute_103-safe)
// ---------------------------------------------------------------------------
__device__ __forceinline__ uint32_t smem_u32(const void* p) {
    uint32_t a;
    asm("{ .reg .u64 t; cvta.to.shared.u64 t, %1; cvt.u32.u64 %0, t; }"
        : "=r"(a) : "l"(p));
    return a;
}
__device__ __forceinline__ void cp_async16(uint32_t dst, const void* src) {
    asm volatile("cp.async.cg.shared.global [%0], [%1], 16;\n"
                 :: "r"(dst), "l"(src) : "memory");
}
__device__ __forceinline__ void cp_commit() {
    asm volatile("cp.async.commit_group;\n" ::: "memory");
}
template <int N>
__device__ __forceinline__ void cp_wait() {
    asm volatile("cp.async.wait_group %0;\n" :: "n"(N) : "memory");
}
__device__ __forceinline__ void ldsm_x4(uint32_t addr, uint32_t* r) {
    asm volatile("ldmatrix.sync.aligned.m8n8.x4.shared.b16 {%0,%1,%2,%3}, [%4];\n"
                 : "=r"(r[0]), "=r"(r[1]), "=r"(r[2]), "=r"(r[3]) : "r"(addr));
}
__device__ __forceinline__ void ldsm_x4t(uint32_t addr, uint32_t* r) {
    asm volatile("ldmatrix.sync.aligned.m8n8.x4.trans.shared.b16 {%0,%1,%2,%3}, [%4];\n"
                 : "=r"(r[0]), "=r"(r[1]), "=r"(r[2]), "=r"(r[3]) : "r"(addr));
}
__device__ __forceinline__ void mma16816(float* c, const uint32_t* a,
                                         uint32_t b0, uint32_t b1) {
    asm volatile(
        "mma.sync.aligned.m16n8k16.row.col.f32.bf16.bf16.f32 "
        "{%0,%1,%2,%3}, {%4,%5,%6,%7}, {%8,%9}, {%0,%1,%2,%3};\n"
        : "+f"(c[0]), "+f"(c[1]), "+f"(c[2]), "+f"(c[3])
        : "r"(a[0]), "r"(a[1]), "r"(a[2]), "r"(a[3]), "r"(b0), "r"(b1));
}
__device__ __forceinline__ void packsplit(float x, float y,
                                          uint32_t& hi, uint32_t& lo) {
    __nv_bfloat162 H = __floats2bfloat162_rn(x, y);
    float2 Hf = __bfloat1622float2(H);
    __nv_bfloat162 L = __floats2bfloat162_rn(x - Hf.x, y - Hf.y);
    hi = *(uint32_t*)&H;
    lo = *(uint32_t*)&L;
}

// ---------------------------------------------------------------------------
// Split conversions for x and W
// ---------------------------------------------------------------------------
__device__ __forceinline__ void split4(float4 v, __nv_bfloat16* h, __nv_bfloat16* l,
                                       size_t idx4) {
    uint32_t h0, l0, h1, l1;
    packsplit(v.x, v.y, h0, l0);
    packsplit(v.z, v.w, h1, l1);
    ((uint32_t*)h)[idx4 * 2 + 0] = h0;
    ((uint32_t*)h)[idx4 * 2 + 1] = h1;
    ((uint32_t*)l)[idx4 * 2 + 0] = l0;
    ((uint32_t*)l)[idx4 * 2 + 1] = l1;
}
__global__ void conv_x(const float* __restrict__ x) {
    size_t i = (size_t)blockIdx.x * blockDim.x + threadIdx.x;
    split4(((const float4*)x)[i], g_XH, g_XL, i);
}
__global__ void conv_w(const float* __restrict__ w0, const float* __restrict__ w1,
                       const float* __restrict__ w2, const float* __restrict__ w3) {
    const float* w = (blockIdx.z == 0) ? w0 : (blockIdx.z == 1) ? w1
                   : (blockIdx.z == 2) ? w2 : w3;
    size_t i = (size_t)blockIdx.x * blockDim.x + threadIdx.x;
    split4(((const float4*)w)[i], g_WH + (size_t)blockIdx.z * DD,
           g_WL + (size_t)blockIdx.z * DD, i);
}

// ---------------------------------------------------------------------------
// Split-bf16 GEMM on mma.sync. 3-stage cp.async pipeline.
// ---------------------------------------------------------------------------
#define BK      64
#define NKT     (D_MODEL / BK)    // 16
#define NTILES  (3 * NKT)         // 48
#define A_BYTES (128 * 128)       // 16384
#define STAGE   (2 * A_BYTES)     // 32768
#define SM_GEMM (3 * STAGE)       // 98304

__device__ __forceinline__ void gemm_core(const __nv_bfloat16* __restrict__ Bh,
                                          const __nv_bfloat16* __restrict__ Bl,
                                          float* __restrict__ Cf,
                                          __nv_bfloat16* __restrict__ Ch,
                                          __nv_bfloat16* __restrict__ Cl,
                                          float scl)
{
    extern __shared__ char smem[];
    const uint32_t sb = smem_u32(smem);
    const int tid = threadIdx.x;
    const int wid = tid >> 5, lid = tid & 31;
    const int wm  = wid >> 2, wn = wid & 3;
    const int bm  = blockIdx.y * 128, bn = blockIdx.x * 128;

    const __nv_bfloat16* At[3] = { g_XH, g_XH, g_XL };
    const __nv_bfloat16* Bt[3] = { Bh,   Bl,   Bh   };

    const int llo  = lid & 7;
    const int lr15 = lid & 15;
    const int lhiA = lid >> 4;
    const int lk8B = (lid >> 3) & 1;
    uint32_t aRow[4], bRow[2];
#pragma unroll
    for (int i = 0; i < 4; i++) aRow[i] = (uint32_t)(wm * 64 + i * 16 + lr15) * 128;
#pragma unroll
    for (int p = 0; p < 2; p++)
        bRow[p] = A_BYTES + (uint32_t)(wn * 32 + p * 16 + llo + ((lid >> 4) & 1) * 8) * 128;

    float acc[4][4][4];
#pragma unroll
    for (int i = 0; i < 4; i++)
#pragma unroll
        for (int j = 0; j < 4; j++)
#pragma unroll
            for (int q = 0; q < 4; q++) acc[i][j][q] = 0.f;

    auto issue = [&](int t) {
        const int term = t / NKT, kt = t % NKT;
        const __nv_bfloat16* Asrc = At[term] + (size_t)bm * D_MODEL + kt * BK;
        const __nv_bfloat16* Bsrc = Bt[term] + (size_t)bn * D_MODEL + kt * BK;
        const uint32_t st = sb + (uint32_t)(t % 3) * STAGE;
#pragma unroll
        for (int u = 0; u < 8; u++) {
            const int i = tid + u * 256;
            const int which = i >> 10;
            const int j = i & 1023;
            const int r = j >> 3, c = j & 7;
            const __nv_bfloat16* src =
                (which ? Bsrc : Asrc) + (size_t)r * D_MODEL + c * 8;
            const uint32_t dst = st + (uint32_t)which * A_BYTES +
                                 (uint32_t)r * 128 + (uint32_t)((c ^ (r & 7)) << 4);
            cp_async16(dst, src);
        }
        cp_commit();
    };

    issue(0);
    issue(1);
    issue(2);

#pragma unroll 1
    for (int t = 0; t < NTILES; t++) {
        if (t < NTILES - 2)       cp_wait<2>();
        else if (t == NTILES - 2) cp_wait<1>();
        else                      cp_wait<0>();
        __syncthreads();

        const uint32_t st = sb + (uint32_t)(t % 3) * STAGE;
#pragma unroll
        for (int s = 0; s < 4; s++) {
            const uint32_t offA = (uint32_t)(((2 * s + lhiA) ^ llo) << 4);
            const uint32_t offB = (uint32_t)(((2 * s + lk8B) ^ llo) << 4);
            uint32_t a[4][4], b[2][4];
#pragma unroll
            for (int i = 0; i < 4; i++) ldsm_x4(st + aRow[i] + offA, a[i]);
#pragma unroll
            for (int p = 0; p < 2; p++) ldsm_x4(st + bRow[p] + offB, b[p]);
#pragma unroll
            for (int i = 0; i < 4; i++)
#pragma unroll
                for (int j = 0; j < 4; j++)
                    mma16816(acc[i][j], a[i], b[j >> 1][(j & 1) * 2 + 0],
                                               b[j >> 1][(j & 1) * 2 + 1]);
        }
        __syncthreads();
        if (t + 3 < NTILES) issue(t + 3);
    }

    const int g  = lid >> 2;
    const int t2 = (lid & 3) * 2;
#pragma unroll
    for (int i = 0; i < 4; i++) {
        const int row = bm + wm * 64 + i * 16 + g;
#pragma unroll
        for (int j = 0; j < 4; j++) {
            const int col = bn + wn * 32 + j * 8 + t2;
            if (Cf) {
                *(float2*)&Cf[(size_t)row * D_MODEL + col] =
                    make_float2(acc[i][j][0], acc[i][j][1]);
                *(float2*)&Cf[(size_t)(row + 8) * D_MODEL + col] =
                    make_float2(acc[i][j][2], acc[i][j][3]);
            } else {
                uint32_t h, l;
                packsplit(acc[i][j][0] * scl, acc[i][j][1] * scl, h, l);
                *(uint32_t*)&Ch[(size_t)row * D_MODEL + col] = h;
                *(uint32_t*)&Cl[(size_t)row * D_MODEL + col] = l;
                packsplit(acc[i][j][2] * scl, acc[i][j][3] * scl, h, l);
                *(uint32_t*)&Ch[(size_t)(row + 8) * D_MODEL + col] = h;
                *(uint32_t*)&Cl[(size_t)(row + 8) * D_MODEL + col] = l;
            }
        }
    }
}

__global__ void __launch_bounds__(256, 2)
gemm_qkv() {
    const int z = blockIdx.z;
    __nv_bfloat16* Ch = (z == 0) ? g_QH : (z == 1) ? g_KH : g_VH;
    __nv_bfloat16* Cl = (z == 0) ? g_QL : (z == 1) ? g_KL : g_VL;
    const float scl = (z == 0) ? 0.125f : 1.0f;      // fold 1/sqrt(64) into Q
    gemm_core(g_WH + (size_t)z * DD, g_WL + (size_t)z * DD, nullptr, Ch, Cl, scl);
}
__global__ void __launch_bounds__(256, 2)
gemm_o(float* __restrict__ out) {
    gemm_core(g_WH + 3ull * DD, g_WL + 3ull * DD, out, nullptr, nullptr, 1.f);
}

// ---------------------------------------------------------------------------
// Tensor-core causal flash attention (split-bf16, fp32 softmax/accum).
// 64 queries/block, 4 warps. Q staged into stage0 area then overwritten by KV
// (saves 16KB -> 66KB/block -> 3 blocks/SM).
// ---------------------------------------------------------------------------
#define AST 33024                         // stage stride bytes
#define SM_ATTN (2 * AST)                 // 66048

__global__ void __launch_bounds__(128, 3)
attn_mma(const int* __restrict__ mask)
{
    extern __shared__ char smem[];
    const uint32_t sb = smem_u32(smem);
    const int tid = threadIdx.x, wid = tid >> 5, lid = tid & 31;
    const int qt = blockIdx.x, h = blockIdx.y, b = blockIdx.z;
    const int bm = qt * 64;
    const int nt = qt + 1;                // causal: key tiles 0..qt

    // ---- stage Q tile (QH|QL) into stage0 area, build A-fragments ----
    {
#pragma unroll
        for (int u = 0; u < 8; u++) {
            const int i = tid + u * 128;          // 0..1023
            const int arr = i >> 9;               // 0 QH, 1 QL
            const int j = i & 511;
            const int r = j >> 3, c = j & 7;
            const __nv_bfloat16* src = (arr ? g_QL : g_QH) +
                (size_t)(b * SEQ + bm + r) * D_MODEL + h * HEAD_DIM + c * 8;
            cp_async16(sb + (uint32_t)arr * 8192 +
                       (uint32_t)r * 128 + (uint32_t)((c ^ (r & 7)) << 4), src);
        }
        cp_commit();
        cp_wait<0>();
        __syncthreads();
    }
    uint32_t aQh[4][4], aQl[4][4];
#pragma unroll
    for (int ks = 0; ks < 4; ks++) {
        const uint32_t off = (uint32_t)(wid * 16 + (lid & 15)) * 128 +
                             (uint32_t)(((2 * ks + (lid >> 4)) ^ (lid & 7)) << 4);
        ldsm_x4(sb + off, aQh[ks]);
        ldsm_x4(sb + 8192 + off, aQl[ks]);
    }
    __syncthreads();          // Q fragments extracted; stage0 free for KV

    auto issueKV = [&](int ti) {
        const uint32_t st = sb + (uint32_t)(ti & 1) * AST;
        const int t0 = ti * 64;
#pragma unroll
        for (int u = 0; u < 16; u++) {
            const int i = tid + u * 128;          // 0..2047
            const int arr = i >> 9;               // 0 KH 1 KL 2 VH 3 VL
            const int j = i & 511;
            const int r = j >> 3, c = j & 7;
            const __nv_bfloat16* base = (arr == 0) ? g_KH : (arr == 1) ? g_KL
                                      : (arr == 2) ? g_VH : g_VL;
            const __nv_bfloat16* src = base +
                (size_t)(b * SEQ + t0 + r) * D_MODEL + h * HEAD_DIM + c * 8;
            cp_async16(st + (uint32_t)arr * 8192 +
                       (uint32_t)r * 128 + (uint32_t)((c ^ (r & 7)) << 4), src);
        }
        if (tid < 16)
            cp_async16(st + 32768 + tid * 16, mask + b * SEQ + t0 + tid * 4);
        cp_commit();
    };

    issueKV(0);
    if (nt > 1) issueKV(1);

    float oreg[8][4];
#pragma unroll
    for (int j = 0; j < 8; j++)
#pragma unroll
        for (int q = 0; q < 4; q++) oreg[j][q] = 0.f;
    float mA = -1e30f, mB = -1e30f, lA = 0.f, lB = 0.f;
    const int q0 = bm + wid * 16 + (lid >> 2);    // row A global q; row B = q0+8

#pragma unroll 1
    for (int ti = 0; ti < nt; ti++) {
        if (ti == nt - 1) cp_wait<0>(); else cp_wait<1>();
        __syncthreads();
        const uint32_t st = sb + (uint32_t)(ti & 1) * AST;
        const int* msk_s = (const int*)(smem + (ti & 1) * AST + 32768);
        const int t0 = ti * 64;

        // ---- S = Q @ K^T (3 split terms) ----
        float sr[8][4];
#pragma unroll
        for (int j = 0; j < 8; j++)
#pragma unroll
            for (int q = 0; q < 4; q++) sr[j][q] = 0.f;
#pragma unroll
        for (int ks = 0; ks < 4; ks++) {
            uint32_t bh[4][4], bl[4][4];
#pragma unroll
            for (int nb = 0; nb < 4; nb++) {
                const uint32_t row = (uint32_t)(nb * 16 + (lid & 7) + ((lid >> 4) & 1) * 8);
                const uint32_t off = row * 128 +
                    (uint32_t)(((2 * ks + ((lid >> 3) & 1)) ^ (lid & 7)) << 4);
                ldsm_x4(st + off, bh[nb]);
                ldsm_x4(st + 8192 + off, bl[nb]);
            }
#pragma unroll
            for (int j = 0; j < 8; j++) {
                const uint32_t b0h = bh[j >> 1][(j & 1) * 2], b1h = bh[j >> 1][(j & 1) * 2 + 1];
                const uint32_t b0l = bl[j >> 1][(j & 1) * 2], b1l = bl[j >> 1][(j & 1) * 2 + 1];
                mma16816(sr[j], aQh[ks], b0h, b1h);
                mma16816(sr[j], aQh[ks], b0l, b1l);
                mma16816(sr[j], aQl[ks], b0h, b1h);
            }
        }

        // ---- mask + online softmax ----
        const bool diag = (ti == qt);
#pragma unroll
        for (int j = 0; j < 8; j++) {
            const int c = j * 8 + (lid & 3) * 2;      // tile-local key col
            const int kg = t0 + c;
            const int mk0 = msk_s[c], mk1 = msk_s[c + 1];
            if (!mk0) { sr[j][0] = -1e30f; sr[j][2] = -1e30f; }
            if (!mk1) { sr[j][1] = -1e30f; sr[j][3] = -1e30f; }
            if (diag) {
                if (kg     > q0)     sr[j][0] = -1e30f;
                if (kg + 1 > q0)     sr[j][1] = -1e30f;
                if (kg     > q0 + 8) sr[j][2] = -1e30f;
                if (kg + 1 > q0 + 8) sr[j][3] = -1e30f;
            }
        }
        float tmA = -1e30f, tmB = -1e30f;
#pragma unroll
        for (int j = 0; j < 8; j++) {
            tmA = fmaxf(tmA, fmaxf(sr[j][0], sr[j][1]));
            tmB = fmaxf(tmB, fmaxf(sr[j][2], sr[j][3]));
        }
        tmA = fmaxf(tmA, __shfl_xor_sync(0xffffffff, tmA, 1));
        tmA = fmaxf(tmA, __shfl_xor_sync(0xffffffff, tmA, 2));
        tmB = fmaxf(tmB, __shfl_xor_sync(0xffffffff, tmB, 1));
        tmB = fmaxf(tmB, __shfl_xor_sync(0xffffffff, tmB, 2));
        const float nmA = fmaxf(mA, tmA), nmB = fmaxf(mB, tmB);
        const float corrA = __expf(mA - nmA), corrB = __expf(mB - nmB);
        mA = nmA; mB = nmB;
        float sA = 0.f, sB = 0.f;
#pragma unroll
        for (int j = 0; j < 8; j++) {
            sr[j][0] = __expf(sr[j][0] - nmA);
            sr[j][1] = __expf(sr[j][1] - nmA);
            sr[j][2] = __expf(sr[j][2] - nmB);
            sr[j][3] = __expf(sr[j][3] - nmB);
            sA += sr[j][0] + sr[j][1];
            sB += sr[j][2] + sr[j][3];
        }
        sA += __shfl_xor_sync(0xffffffff, sA, 1);
        sA += __shfl_xor_sync(0xffffffff, sA, 2);
        sB += __shfl_xor_sync(0xffffffff, sB, 1);
        sB += __shfl_xor_sync(0xffffffff, sB, 2);
        lA = lA * corrA + sA;
        lB = lB * corrB + sB;
#pragma unroll
        for (int j = 0; j < 8; j++) {
            oreg[j][0] *= corrA; oreg[j][1] *= corrA;
            oreg[j][2] *= corrB; oreg[j][3] *= corrB;
        }

        // ---- O += P @ V (3 split terms) ----
#pragma unroll
        for (int ks = 0; ks < 4; ks++) {
            uint32_t aph[4], apl[4];
            packsplit(sr[2*ks][0],   sr[2*ks][1],   aph[0], apl[0]);
            packsplit(sr[2*ks][2],   sr[2*ks][3],   aph[1], apl[1]);
            packsplit(sr[2*ks+1][0], sr[2*ks+1][1], aph[2], apl[2]);
            packsplit(sr[2*ks+1][2], sr[2*ks+1][3], aph[3], apl[3]);
            uint32_t vh[4][4], vl[4][4];
#pragma unroll
            for (int nb = 0; nb < 4; nb++) {
                const uint32_t row = (uint32_t)(ks * 16 + (lid & 7) + ((lid >> 3) & 1) * 8);
                const uint32_t chk = (uint32_t)(nb * 2 + (lid >> 4));
                const uint32_t off = row * 128 + ((chk ^ (lid & 7)) << 4);
                ldsm_x4t(st + 16384 + off, vh[nb]);
                ldsm_x4t(st + 24576 + off, vl[nb]);
            }
#pragma unroll
            for (int j = 0; j < 8; j++) {
                const uint32_t b0h = vh[j >> 1][(j & 1) * 2], b1h = vh[j >> 1][(j & 1) * 2 + 1];
                const uint32_t b0l = vl[j >> 1][(j & 1) * 2], b1l = vl[j >> 1][(j & 1) * 2 + 1];
                mma16816(oreg[j], aph, b0h, b1h);
                mma16816(oreg[j], apl, b0h, b1h);
                mma16816(oreg[j], aph, b0l, b1l);
            }
        }

        __syncthreads();
        if (ti + 2 < nt) issueKV(ti + 2);
    }

    // ---- epilogue: normalize, split to bf16 h/l, write to g_XH/g_XL ----
    const float invA = 1.f / lA, invB = 1.f / lB;
    const size_t rA = (size_t)(b * SEQ + q0) * D_MODEL + h * HEAD_DIM;
    const size_t rB = rA + 8ull * D_MODEL;
#pragma unroll
    for (int j = 0; j < 8; j++) {
        const int col = j * 8 + (lid & 3) * 2;
        uint32_t hh, ll;
        packsplit(oreg[j][0] * invA, oreg[j][1] * invA, hh, ll);
        *(uint32_t*)&g_XH[rA + col] = hh;
        *(uint32_t*)&g_XL[rA + col] = ll;
        packsplit(oreg[j][2] * invB, oreg[j][3] * invB, hh, ll);
        *(uint32_t*)&g_XH[rB + col] = hh;
        *(uint32_t*)&g_XL[rB + col] = ll;
    }
}

// ---------------------------------------------------------------------------
// Launch. Inputs: x, attention_mask, wq, wk, wv, wo. Output fp32.
// ---------------------------------------------------------------------------
extern "C" void kernel_launch(void* const* d_in, const int* in_sizes, int n_in,
                              void* d_out, int out_size)
{
    const float* x    = (const float*)d_in[0];
    const int*   amsk = (const int*)  d_in[1];
    const float* wq   = (const float*)d_in[2];
    const float* wk   = (const float*)d_in[3];
    const float* wv   = (const float*)d_in[4];
    const float* wo   = (const float*)d_in[5];
    float*       out  = (float*)d_out;

    cudaFuncSetAttribute(gemm_qkv, cudaFuncAttributeMaxDynamicSharedMemorySize, SM_GEMM);
    cudaFuncSetAttribute(gemm_o,   cudaFuncAttributeMaxDynamicSharedMemorySize, SM_GEMM);
    cudaFuncSetAttribute(attn_mma, cudaFuncAttributeMaxDynamicSharedMemorySize, SM_ATTN);

    conv_x<<<M_ROWS * D_MODEL / 4 / 256, 256>>>(x);
    conv_w<<<dim3(DD / 4 / 256, 1, 4), 256>>>(wq, wk, wv, wo);

    dim3 gQKV(D_MODEL / 128, M_ROWS / 128, 3);   // (8, 64, 3)
    gemm_qkv<<<gQKV, 256, SM_GEMM>>>();

    dim3 gAttn(SEQ / 64, N_HEADS, BATCH);        // (32, 16, 4)
    attn_mma<<<gAttn, 128, SM_ATTN>>>(amsk);

    dim3 gOut(D_MODEL / 128, M_ROWS / 128, 1);
    gemm_o<<<gOut, 256, SM_GEMM>>>(out);
}